// round 15
// baseline (speedup 1.0000x reference)
#include <cuda_runtime.h>
#include <cuda_fp16.h>
#include <cstdint>
#include <math.h>

#define EPSF 1e-5f

constexpr int B_  = 2, T_ = 16, S_ = 256, C_ = 1024, H_ = 16;
constexpr int R_  = B_ * T_ * S_;   // 8192 tokens
constexpr int HID_ = 4 * C_;        // 4096
constexpr float SCALE_ = 8.0f / 64.0f;

// ---- scratch (device globals; no runtime allocation allowed) ----
__device__ float  g_xbuf[R_ * C_];
__device__ __half g_xln [R_ * C_];
__device__ __half g_qkv [R_ * 3 * C_];
__device__ __half g_attn[R_ * C_];
__device__ __half g_h   [R_ * HID_];
// transposed (fp16) weights, [N,K] row-major
__device__ __half g_wt_sqkv [3 * C_ * C_];
__device__ __half g_wt_sproj[C_ * C_];
__device__ __half g_wt_tqkv [3 * C_ * C_];
__device__ __half g_wt_tproj[C_ * C_];
__device__ __half g_wt_fc1  [HID_ * C_];
__device__ __half g_wt_fc2  [C_ * HID_];

__device__ __forceinline__ uint32_t smem_u32(const void* p) {
    uint32_t a;
    asm("{ .reg .u64 t; cvta.to.shared.u64 t, %1; cvt.u32.u64 %0, t; }" : "=r"(a) : "l"(p));
    return a;
}
// e^(s-8) entirely on fma/alu pipes. Valid for s in [-40, 40].
__device__ __forceinline__ float fexp_shift(float s) {
    const float y = fmaf(s, 1.44269504089f, -11.5415603272f);
    const int   i = __float2int_rn(y);
    const float f = y - (float)i;
    float p = fmaf(f, 0.00133335581f, 0.00961812910f);
    p = fmaf(f, p, 0.0555041087f);
    p = fmaf(f, p, 0.240226507f);
    p = fmaf(f, p, 0.693147181f);
    p = fmaf(f, p, 1.0f);
    return __int_as_float(__float_as_int(p) + (i << 23));
}
__device__ __forceinline__ void ldsm4(uint32_t& r0, uint32_t& r1, uint32_t& r2,
                                      uint32_t& r3, uint32_t addr) {
    asm volatile("ldmatrix.sync.aligned.m8n8.x4.b16 {%0,%1,%2,%3}, [%4];"
        : "=r"(r0), "=r"(r1), "=r"(r2), "=r"(r3) : "r"(addr));
}
__device__ __forceinline__ void mma_f16(float c[4], const uint32_t a[4], const uint32_t b[2]) {
    asm volatile("mma.sync.aligned.m16n8k16.row.col.f32.f16.f16.f32 "
        "{%0,%1,%2,%3}, {%4,%5,%6,%7}, {%8,%9}, {%0,%1,%2,%3};"
        : "+f"(c[0]), "+f"(c[1]), "+f"(c[2]), "+f"(c[3])
        : "r"(a[0]), "r"(a[1]), "r"(a[2]), "r"(a[3]), "r"(b[0]), "r"(b[1]));
}
__device__ __forceinline__ uint32_t h2pack(float a, float b) {
    __half2 h = __floats2half2_rn(a, b);
    return *(uint32_t*)&h;
}

// ============================================================
// LN body (warp-per-row) shared by ln_kernel and the fused
// startup kernel.
// ============================================================
template<bool PERM>
__device__ __forceinline__ void ln_row(const float* __restrict__ in,
                                       __half* __restrict__ out,
                                       const float* __restrict__ w,
                                       const float* __restrict__ b,
                                       int row, int lane)
{
    int in_row = row;
    if (PERM) {
        const int t = row & 15, s = (row >> 4) & 255, bb = row >> 12;
        in_row = bb * 4096 + t * 256 + s;
    }
    const float4* ip = reinterpret_cast<const float4*>(in + (size_t)in_row * 1024);

    float4 xv[8];
    float s = 0.f, ss = 0.f;
    #pragma unroll
    for (int i = 0; i < 8; i++) {
        xv[i] = ip[lane + 32 * i];
        s  += xv[i].x + xv[i].y + xv[i].z + xv[i].w;
        ss += xv[i].x*xv[i].x + xv[i].y*xv[i].y + xv[i].z*xv[i].z + xv[i].w*xv[i].w;
    }
    #pragma unroll
    for (int o = 16; o; o >>= 1) {
        s  += __shfl_xor_sync(0xffffffffu, s,  o);
        ss += __shfl_xor_sync(0xffffffffu, ss, o);
    }
    const float mean = s * (1.f / 1024.f);
    const float rstd = rsqrtf(ss * (1.f / 1024.f) - mean * mean + EPSF);

    const float4* wp = reinterpret_cast<const float4*>(w);
    const float4* bp = reinterpret_cast<const float4*>(b);
    uint2* op = reinterpret_cast<uint2*>(out + (size_t)row * 1024);
    #pragma unroll
    for (int i = 0; i < 8; i++) {
        const float4 wv = wp[lane + 32 * i];
        const float4 bv = bp[lane + 32 * i];
        uint2 pk;
        pk.x = h2pack((xv[i].x - mean) * rstd * wv.x + bv.x,
                      (xv[i].y - mean) * rstd * wv.y + bv.y);
        pk.y = h2pack((xv[i].z - mean) * rstd * wv.z + bv.z,
                      (xv[i].w - mean) * rstd * wv.w + bv.w);
        op[lane + 32 * i] = pk;
    }
}

template<bool PERM>
__global__ void ln_kernel(const float* __restrict__ in, __half* __restrict__ out,
                          const float* __restrict__ w, const float* __restrict__ b)
{
    ln_row<PERM>(in, out, w, b, blockIdx.x * 8 + (threadIdx.x >> 5), threadIdx.x & 31);
}

// ============================================================
// Fused STARTUP kernel: blocks [0, R_/8) do the first LN (x->xln);
// blocks >= R_/8 do the 6 weight transposes (independent work,
// one launch, runs concurrently).
// ============================================================
struct TWJob { const float* in; __half* out; int K; int N; int ntx; int base; };
struct TWPack {
    TWJob j[6];
    const float* ln_in; __half* ln_out; const float* ln_w; const float* ln_b;
};

__global__ void startup_kernel(TWPack p)
{
    const int LNB = R_ / 8;
    if ((int)blockIdx.x < LNB) {
        ln_row<false>(p.ln_in, p.ln_out, p.ln_w, p.ln_b,
                      blockIdx.x * 8 + (threadIdx.x >> 5), threadIdx.x & 31);
        return;
    }
    __shared__ float t[32][33];
    const int bt = blockIdx.x - LNB;
    int ji = 0;
    #pragma unroll
    for (int i = 1; i < 6; i++)
        if (bt >= p.j[i].base) ji = i;
    const TWJob& J = p.j[ji];
    const int lt = bt - J.base;
    const int n0 = (lt % J.ntx) * 32;
    const int k0 = (lt / J.ntx) * 32;
    const int tid = threadIdx.x;
    const int x = tid & 31, y = tid >> 5;
    #pragma unroll
    for (int i = 0; i < 32; i += 8)
        t[y + i][x] = J.in[(size_t)(k0 + y + i) * J.N + n0 + x];
    __syncthreads();
    #pragma unroll
    for (int i = 0; i < 32; i += 8)
        J.out[(size_t)(n0 + y + i) * J.K + k0 + x] = __float2half_rn(t[x][y + i]);
}

// ============================================================
// Spatial attention, all-fp16 tensor cores (unchanged R14).
// M-SPLIT: 2 CTAs per (batch,head), 128 query rows each.
// ============================================================
constexpr int ATTN_SMEM = 16384 + 32768 + 32768;   // 80 KB

__global__ __launch_bounds__(256, 2) void attn_tc(const __half* __restrict__ qkv,
                                                  __half* __restrict__ out)
{
    extern __shared__ float smf[];
    char* smc = (char*)smf;
    const uint32_t Qs = smem_u32(smf);
    const uint32_t Ks = Qs + 16384;
    const uint32_t Vt = Qs + 49152;

    const int tid = threadIdx.x, wid = tid >> 5, lane = tid & 31;
    const int g = lane >> 2, tig = lane & 3;
    const int bx = blockIdx.x;
    const int piece = bx & 1;
    const int bh = bx >> 1, h = bh & 15, batch = bh >> 4;
    const __half* base = qkv + (size_t)batch * 256 * 3072;

    #pragma unroll
    for (int t = 0; t < 4; t++) {
        const int idx = tid + (t << 8);
        const int r = idx >> 3, c = idx & 7;
        const uint32_t dst = (uint32_t)(r * 128 + ((c ^ (r & 7)) << 4));
        const uint4 qv = *(const uint4*)(base + (size_t)(piece * 128 + r) * 3072 + h * 64 + c * 8);
        *(uint4*)(smc + dst) = qv;
    }
    #pragma unroll
    for (int t = 0; t < 8; t++) {
        const int idx = tid + (t << 8);
        const int r = idx >> 3, c = idx & 7;
        const uint32_t dst = (uint32_t)(r * 128 + ((c ^ (r & 7)) << 4));
        const uint4 kv = *(const uint4*)(base + (size_t)r * 3072 + 1024 + h * 64 + c * 8);
        *(uint4*)(smc + 16384 + dst) = kv;
        uint4 vv = *(const uint4*)(base + (size_t)r * 3072 + 2048 + h * 64 + c * 8);
        __half hv[8];
        *(uint4*)hv = vv;
        const int kc = r >> 3, kb = r & 7;
        #pragma unroll
        for (int i = 0; i < 8; i++) {
            const int d = c * 8 + i;
            const uint32_t vc = (uint32_t)((kc & 24) | ((kc ^ d) & 7));
            *(__half*)(smc + 49152 + d * 512 + (vc << 4) + kb * 2) = hv[i];
        }
    }
    __syncthreads();

    const int lr = lane & 7;
    const int aRow = wid * 16 + ((lane >> 3) & 1) * 8 + lr;
    const int cbA = lane >> 4;
    uint32_t qf[4][4];
    #pragma unroll
    for (int ks = 0; ks < 4; ks++)
        ldsm4(qf[ks][0], qf[ks][1], qf[ks][2], qf[ks][3],
              Qs + (uint32_t)(aRow * 128) +
              (((uint32_t)(2 * ks + cbA) ^ (uint32_t)lr) << 4));

    const int bRow = (lane >> 4) * 8 + lr;
    const int cbB = (lane >> 3) & 1;

    float o[8][4];
    float rs[2] = {0.f, 0.f};
    #pragma unroll
    for (int no = 0; no < 8; no++)
        #pragma unroll
        for (int i = 0; i < 4; i++) o[no][i] = 0.f;

    for (int tile = 0; tile < 8; tile++) {
        float s[4][4];
        #pragma unroll
        for (int nt = 0; nt < 4; nt++)
            #pragma unroll
            for (int i = 0; i < 4; i++) s[nt][i] = 0.f;
        #pragma unroll
        for (int ks = 0; ks < 4; ks++) {
            uint32_t kb_[4][2];
            #pragma unroll
            for (int ntp = 0; ntp < 2; ntp++)
                ldsm4(kb_[2*ntp][0], kb_[2*ntp][1], kb_[2*ntp+1][0], kb_[2*ntp+1][1],
                      Ks + (uint32_t)((tile * 32 + bRow + ntp * 16) * 128) +
                      (((uint32_t)(2 * ks + cbB) ^ (uint32_t)lr) << 4));
            #pragma unroll
            for (int nt = 0; nt < 4; nt++)
                mma_f16(s[nt], qf[ks], kb_[nt]);
        }
        #pragma unroll
        for (int nt = 0; nt < 4; nt++)
            #pragma unroll
            for (int i = 0; i < 4; i++) {
                const float e = fexp_shift(s[nt][i]);
                rs[i >> 1] += e;
                s[nt][i] = e;
            }
        #pragma unroll
        for (int kk = 0; kk < 2; kk++) {
            uint32_t vb[8][2];
            const uint32_t c0 = (uint32_t)(tile * 4 + kk * 2 + cbB);
            #pragma unroll
            for (int ntp = 0; ntp < 4; ntp++) {
                const uint32_t row = (uint32_t)(bRow + ntp * 16);
                const uint32_t vc = (c0 & 24) | ((c0 ^ (uint32_t)lr) & 7);
                ldsm4(vb[2*ntp][0], vb[2*ntp][1], vb[2*ntp+1][0], vb[2*ntp+1][1],
                      Vt + row * 512 + (vc << 4));
            }
            uint32_t pa[4];
            pa[0] = h2pack(s[2*kk][0],   s[2*kk][1]);
            pa[1] = h2pack(s[2*kk][2],   s[2*kk][3]);
            pa[2] = h2pack(s[2*kk+1][0], s[2*kk+1][1]);
            pa[3] = h2pack(s[2*kk+1][2], s[2*kk+1][3]);
            #pragma unroll
            for (int no = 0; no < 8; no++)
                mma_f16(o[no], pa, vb[no]);
        }
    }

    #pragma unroll
    for (int i = 0; i < 2; i++) {
        float v = rs[i];
        v += __shfl_xor_sync(0xffffffffu, v, 1);
        v += __shfl_xor_sync(0xffffffffu, v, 2);
        rs[i] = 1.f / v;
    }
    const int r0 = piece * 128 + wid * 16 + g;
    __half* p0 = out + ((size_t)batch * 256 + r0) * 1024 + h * 64;
    __half* p1 = p0 + 8 * 1024;
    #pragma unroll
    for (int no = 0; no < 8; no++) {
        *(uint32_t*)(p0 + no * 8 + tig * 2) =
            h2pack(o[no][0] * rs[0], o[no][1] * rs[0]);
        *(uint32_t*)(p1 + no * 8 + tig * 2) =
            h2pack(o[no][2] * rs[1], o[no][3] * rs[1]);
    }
}

// ============================================================
// Temporal attention (N=16), fp16 in/out, fp32 accumulate.
// ============================================================
__global__ void attn16_kernel(const __half* __restrict__ qkv, __half* __restrict__ out)
{
    constexpr int N = 16;
    const int tid = threadIdx.x;
    const int bh = blockIdx.x * 16 + (tid >> 4);
    const int h = bh & 15;
    const int batch = bh >> 4;
    const int row = tid & 15;
    const __half* base = qkv + (size_t)batch * N * 3072;

    __half2 q2[32];
    {
        const uint4* qp = reinterpret_cast<const uint4*>(base + (size_t)row * 3072 + h * 64);
        #pragma unroll
        for (int c = 0; c < 8; c++) *(uint4*)(q2 + c * 4) = qp[c];
    }

    float2 acc[32];
    #pragma unroll
    for (int d = 0; d < 32; d++) acc[d] = make_float2(0.f, 0.f);
    float sum = 0.f;
    #pragma unroll
    for (int j = 0; j < N; j++) {
        __half2 k2[32];
        const uint4* kp = reinterpret_cast<const uint4*>(base + (size_t)j * 3072 + 1024 + h * 64);
        #pragma unroll
        for (int c = 0; c < 8; c++) *(uint4*)(k2 + c * 4) = kp[c];
        float s = 0.f;
        #pragma unroll
        for (int d = 0; d < 32; d++) {
            const float2 qd = __half22float2(q2[d]);
            const float2 kd = __half22float2(k2[d]);
            s += qd.x * kd.x + qd.y * kd.y;
        }
        const float e = fexp_shift(s);
        sum += e;
        __half2 v2[32];
        const uint4* vp = reinterpret_cast<const uint4*>(base + (size_t)j * 3072 + 2048 + h * 64);
        #pragma unroll
        for (int c = 0; c < 8; c++) *(uint4*)(v2 + c * 4) = vp[c];
        #pragma unroll
        for (int d = 0; d < 32; d++) {
            const float2 vd = __half22float2(v2[d]);
            acc[d].x += e * vd.x;
            acc[d].y += e * vd.y;
        }
    }
    const float inv = 1.f / sum;
    uint32_t* op = reinterpret_cast<uint32_t*>(out + ((size_t)batch * N + row) * 1024 + h * 64);
    #pragma unroll
    for (int d = 0; d < 32; d++)
        op[d] = h2pack(acc[d].x * inv, acc[d].y * inv);
}

// ============================================================
// fp16 tensor-core GEMM: 128x128 block, 32x64 warp tiles,
// 3-stage cp.async pipeline, one barrier per K-iteration,
// peeled last iteration.
// ============================================================
constexpr int STG_B    = 32768;           // A 16KB + B 16KB
constexpr int GEMM_SMEM = 3 * STG_B;      // 96 KB

template<bool GELU, bool HALFOUT, bool PERMROW, bool QKVLN>
__global__ __launch_bounds__(256, 2) void gemm_mma(
    const __half* __restrict__ A, const __half* __restrict__ Bt,
    void* __restrict__ Cv, const float* __restrict__ bias,
    const float* __restrict__ resid, int M, int N, int K,
    const float* __restrict__ hn_w, const float* __restrict__ hn_b, float qscale)
{
    extern __shared__ float sm[];
    const uint32_t stg = smem_u32(sm);

    const int tid = threadIdx.x;
    const int wid = tid >> 5, lane = tid & 31;
    const int g = lane >> 2, tig = lane & 3;
    const int warpM = wid & 3, warpN = wid >> 2;
    const int bx = blockIdx.x, by = blockIdx.y;
    const int NKB = K >> 6;

    uint32_t a_s[4], b_s[4];
    const __half *a_g[4], *b_g[4];
    #pragma unroll
    for (int t = 0; t < 4; t++) {
        const int idx = tid + (t << 8);
        const int r = idx >> 3, c = idx & 7;
        const uint32_t sw = (uint32_t)(r * 128 + ((c ^ (r & 7)) << 4));
        a_s[t] = sw;            b_s[t] = sw + 16384;
        a_g[t] = A  + (size_t)(by * 128 + r) * K + c * 8;
        b_g[t] = Bt + (size_t)(bx * 128 + r) * K + c * 8;
    }

    auto load_stage = [&](int s, int kb) {
        const uint32_t sb = stg + s * STG_B;
        const int ko = kb << 6;
        #pragma unroll
        for (int t = 0; t < 4; t++)
            asm volatile("cp.async.cg.shared.global [%0], [%1], 16;" ::
                "r"(sb + a_s[t]), "l"(a_g[t] + ko) : "memory");
        #pragma unroll
        for (int t = 0; t < 4; t++)
            asm volatile("cp.async.cg.shared.global [%0], [%1], 16;" ::
                "r"(sb + b_s[t]), "l"(b_g[t] + ko) : "memory");
    };

    const int lr = lane & 7;
    const int aRow = warpM * 32 + ((lane >> 3) & 1) * 8 + lr;
    const int cbA  = lane >> 4;
    const uint32_t aRx = (uint32_t)(aRow * 128);
    const uint32_t a7  = (uint32_t)(aRow & 7);
    const int bRow = warpN * 64 + (lane >> 4) * 8 + lr;
    const int cbB  = (lane >> 3) & 1;
    const uint32_t bRx = (uint32_t)(bRow * 128);
    const uint32_t b7  = (uint32_t)(bRow & 7);

    float acc[2][8][4];
    #pragma unroll
    for (int mt = 0; mt < 2; mt++)
        #pragma unroll
        for (int nt = 0; nt < 8; nt++)
            #pragma unroll
            for (int i = 0; i < 4; i++) acc[mt][nt][i] = 0.f;

    load_stage(0, 0);
    asm volatile("cp.async.commit_group;" ::: "memory");
    load_stage(1, 1);
    asm volatile("cp.async.commit_group;" ::: "memory");

    auto compute_stage = [&](int sidx) {
        const uint32_t sA = stg + sidx * STG_B;
        const uint32_t sB = sA + 16384;
        #pragma unroll
        for (int ks = 0; ks < 4; ks++) {
            uint32_t a[2][4], b[8][2];
            const uint32_t swA = ((uint32_t)(2 * ks + cbA) ^ a7) << 4;
            #pragma unroll
            for (int mt = 0; mt < 2; mt++)
                ldsm4(a[mt][0], a[mt][1], a[mt][2], a[mt][3],
                      sA + aRx + (uint32_t)(mt * 16 * 128) + swA);
            const uint32_t swB = ((uint32_t)(2 * ks + cbB) ^ b7) << 4;
            #pragma unroll
            for (int ntp = 0; ntp < 4; ntp++)
                ldsm4(b[2 * ntp][0], b[2 * ntp][1], b[2 * ntp + 1][0], b[2 * ntp + 1][1],
                      sB + bRx + (uint32_t)(ntp * 16 * 128) + swB);
            #pragma unroll
            for (int mt = 0; mt < 2; mt++)
                #pragma unroll
                for (int nt = 0; nt < 8; nt++)
                    mma_f16(acc[mt][nt], a[mt], b[nt]);
        }
    };

    int sidx = 0;
    for (int kb = 0; kb < NKB - 1; kb++) {
        asm volatile("cp.async.wait_group 1;" ::: "memory");
        __syncthreads();
        compute_stage(sidx);
        if (kb + 2 < NKB) {
            const int s2 = (sidx + 2 >= 3) ? sidx - 1 : sidx + 2;
            load_stage(s2, kb + 2);
        }
        asm volatile("cp.async.commit_group;" ::: "memory");
        sidx = (sidx + 1 == 3) ? 0 : sidx + 1;
    }
    asm volatile("cp.async.wait_group 0;" ::: "memory");
    __syncthreads();
    compute_stage(sidx);

    // ---- epilogue ----
    const int colblk = bx * 128 + warpN * 64;
    const int which = QKVLN ? (colblk >> 10) : 2;   // 0 q, 1 k, 2 v
    const float lnscale = (which == 0) ? qscale : 1.f;

    #pragma unroll
    for (int mt = 0; mt < 2; mt++) {
        #pragma unroll
        for (int half = 0; half < 2; half++) {
            int row = by * 128 + warpM * 32 + mt * 16 + g + half * 8;
            if (PERMROW) {
                const int t = row & 15, s = (row >> 4) & 255, bb = row >> 12;
                row = bb * 4096 + t * 256 + s;
            }
            float mean = 0.f, rstd = 1.f;
            if (QKVLN && which < 2) {
                float s1 = 0.f, s2 = 0.f;
                #pragma unroll
                for (int nt = 0; nt < 8; nt++) {
                    const float u0 = acc[mt][nt][half * 2 + 0];
                    const float u1 = acc[mt][nt][half * 2 + 1];
                    s1 += u0 + u1;
                    s2 += u0 * u0 + u1 * u1;
                }
                s1 += __shfl_xor_sync(0xffffffffu, s1, 1);
                s2 += __shfl_xor_sync(0xffffffffu, s2, 1);
                s1 += __shfl_xor_sync(0xffffffffu, s1, 2);
                s2 += __shfl_xor_sync(0xffffffffu, s2, 2);
                mean = s1 * (1.f / 64.f);
                rstd = rsqrtf(s2 * (1.f / 64.f) - mean * mean + EPSF);
            }
            const float* rp = resid ? resid + (size_t)row * N : nullptr;
            #pragma unroll
            for (int nt = 0; nt < 8; nt++) {
                const int col = colblk + nt * 8 + tig * 2;
                float v0 = acc[mt][nt][half * 2 + 0];
                float v1 = acc[mt][nt][half * 2 + 1];
                if (QKVLN) {
                    if (which < 2) {
                        const int hc = nt * 8 + tig * 2;
                        v0 = ((v0 - mean) * rstd * hn_w[hc]     + hn_b[hc])     * lnscale;
                        v1 = ((v1 - mean) * rstd * hn_w[hc + 1] + hn_b[hc + 1]) * lnscale;
                    }
                } else {
                    if (bias) { v0 += bias[col]; v1 += bias[col + 1]; }
                    if (rp)   { v0 += rp[col];   v1 += rp[col + 1]; }
                    if (GELU) {
                        v0 = 0.5f * v0 * (1.f + erff(v0 * 0.70710678f));
                        v1 = 0.5f * v1 * (1.f + erff(v1 * 0.70710678f));
                    }
                }
                if (HALFOUT) {
                    __half* cp = (__half*)Cv + (size_t)row * N + col;
                    *(uint32_t*)cp = h2pack(v0, v1);
                } else {
                    float* cp = (float*)Cv + (size_t)row * N + col;
                    float2 v; v.x = v0; v.y = v1;
                    *(float2*)cp = v;
                }
            }
        }
    }
}

// ============================================================
extern "C" void kernel_launch(void* const* d_in, const int* /*in_sizes*/, int /*n_in*/,
                              void* d_out, int /*out_size*/)
{
    const float* x        = (const float*)d_in[0];
    const float* ns_w     = (const float*)d_in[1];
    const float* ns_b     = (const float*)d_in[2];
    const float* nt_w     = (const float*)d_in[3];
    const float* nt_b     = (const float*)d_in[4];
    const float* nm_w     = (const float*)d_in[5];
    const float* nm_b     = (const float*)d_in[6];
    const float* s_qkv    = (const float*)d_in[7];
    const float* s_qkn_w  = (const float*)d_in[8];
    const float* s_qkn_b  = (const float*)d_in[9];
    const float* s_proj_w = (const float*)d_in[10];
    const float* s_proj_b = (const float*)d_in[11];
    const float* t_qkv    = (const float*)d_in[12];
    const float* t_qkn_w  = (const float*)d_in[13];
    const float* t_qkn_b  = (const float*)d_in[14];
    const float* t_proj_w = (const float*)d_in[15];
    const float* t_proj_b = (const float*)d_in[16];
    const float* fc1_w    = (const float*)d_in[17];
    const float* fc1_b    = (const float*)d_in[18];
    const float* fc2_w    = (const float*)d_in[19];
    const float* fc2_b    = (const float*)d_in[20];
    float* out = (float*)d_out;

    float *xbuf;
    __half *xln, *qkv, *attn, *hbuf;
    __half *wt_sqkv, *wt_sproj, *wt_tqkv, *wt_tproj, *wt_fc1, *wt_fc2;
    cudaGetSymbolAddress((void**)&xbuf, g_xbuf);
    cudaGetSymbolAddress((void**)&xln,  g_xln);
    cudaGetSymbolAddress((void**)&qkv,  g_qkv);
    cudaGetSymbolAddress((void**)&attn, g_attn);
    cudaGetSymbolAddress((void**)&hbuf, g_h);
    cudaGetSymbolAddress((void**)&wt_sqkv,  g_wt_sqkv);
    cudaGetSymbolAddress((void**)&wt_sproj, g_wt_sproj);
    cudaGetSymbolAddress((void**)&wt_tqkv,  g_wt_tqkv);
    cudaGetSymbolAddress((void**)&wt_tproj, g_wt_tproj);
    cudaGetSymbolAddress((void**)&wt_fc1,   g_wt_fc1);
    cudaGetSymbolAddress((void**)&wt_fc2,   g_wt_fc2);

    cudaFuncSetAttribute(attn_tc, cudaFuncAttributeMaxDynamicSharedMemorySize, ATTN_SMEM);
    cudaFuncSetAttribute((const void*)gemm_mma<false, false, false, false>,
                         cudaFuncAttributeMaxDynamicSharedMemorySize, GEMM_SMEM);
    cudaFuncSetAttribute((const void*)gemm_mma<false, true,  false, true>,
                         cudaFuncAttributeMaxDynamicSharedMemorySize, GEMM_SMEM);
    cudaFuncSetAttribute((const void*)gemm_mma<false, false, true,  false>,
                         cudaFuncAttributeMaxDynamicSharedMemorySize, GEMM_SMEM);
    cudaFuncSetAttribute((const void*)gemm_mma<true,  true,  false, false>,
                         cudaFuncAttributeMaxDynamicSharedMemorySize, GEMM_SMEM);

    // ---- fused startup: first LN + all 6 weight transposes ----
    TWPack pk;
    int base = 0;
    auto mk = [&](const float* in, __half* o, int K, int N) {
        TWJob j; j.in = in; j.out = o; j.K = K; j.N = N; j.ntx = N / 32; j.base = base;
        base += (N / 32) * (K / 32);
        return j;
    };
    pk.j[0] = mk(s_qkv,    wt_sqkv,  1024, 3072);
    pk.j[1] = mk(s_proj_w, wt_sproj, 1024, 1024);
    pk.j[2] = mk(t_qkv,    wt_tqkv,  1024, 3072);
    pk.j[3] = mk(t_proj_w, wt_tproj, 1024, 1024);
    pk.j[4] = mk(fc1_w,    wt_fc1,   1024, 4096);
    pk.j[5] = mk(fc2_w,    wt_fc2,   4096, 1024);
    pk.ln_in = x; pk.ln_out = xln; pk.ln_w = ns_w; pk.ln_b = ns_b;
    startup_kernel<<<R_ / 8 + base, 256>>>(pk);

    // ---- spatial attention block ----
    gemm_mma<false, true, false, true><<<dim3(24, 64), 256, GEMM_SMEM>>>(
        xln, wt_sqkv, qkv, nullptr, nullptr, R_, 3072, 1024, s_qkn_w, s_qkn_b, SCALE_);
    attn_tc<<<B_ * T_ * H_ * 2, 256, ATTN_SMEM>>>(qkv, attn);
    gemm_mma<false, false, false, false><<<dim3(8, 64), 256, GEMM_SMEM>>>(
        attn, wt_sproj, xbuf, s_proj_b, x, R_, 1024, 1024, nullptr, nullptr, 1.f);

    // ---- temporal attention block (permutes fused into ln + gemm) ----
    ln_kernel<true><<<R_ / 8, 256>>>(xbuf, xln, nt_w, nt_b);
    gemm_mma<false, true, false, true><<<dim3(24, 64), 256, GEMM_SMEM>>>(
        xln, wt_tqkv, qkv, nullptr, nullptr, R_, 3072, 1024, t_qkn_w, t_qkn_b, SCALE_);
    attn16_kernel<<<(B_ * S_ * H_) / 16, 256>>>(qkv, attn);
    gemm_mma<false, false, true, false><<<dim3(8, 64), 256, GEMM_SMEM>>>(
        attn, wt_tproj, xbuf, t_proj_b, xbuf, R_, 1024, 1024, nullptr, nullptr, 1.f);

    // ---- MLP ----
    ln_kernel<false><<<R_ / 8, 256>>>(xbuf, xln, nm_w, nm_b);
    gemm_mma<true,  true,  false, false><<<dim3(32, 64), 256, GEMM_SMEM>>>(
        xln, wt_fc1, hbuf, fc1_b, nullptr, R_, 4096, 1024, nullptr, nullptr, 1.f);
    gemm_mma<false, false, false, false><<<dim3(8, 64), 256, GEMM_SMEM>>>(
        hbuf, wt_fc2, out, fc2_b, xbuf, R_, 1024, 4096, nullptr, nullptr, 1.f);
}

// round 16
// speedup vs baseline: 1.0183x; 1.0183x over previous
#include <cuda_runtime.h>
#include <cuda_fp16.h>
#include <cstdint>
#include <math.h>

#define EPSF 1e-5f

constexpr int B_  = 2, T_ = 16, S_ = 256, C_ = 1024, H_ = 16;
constexpr int R_  = B_ * T_ * S_;   // 8192 tokens
constexpr int HID_ = 4 * C_;        // 4096
constexpr float SCALE_ = 8.0f / 64.0f;

// ---- scratch (device globals; no runtime allocation allowed) ----
__device__ float  g_xbuf[R_ * C_];
__device__ __half g_xln [R_ * C_];
__device__ __half g_qkv [R_ * 3 * C_];
__device__ __half g_attn[R_ * C_];
__device__ __half g_h   [R_ * HID_];
// transposed (fp16) weights, [N,K] row-major
__device__ __half g_wt_sqkv [3 * C_ * C_];
__device__ __half g_wt_sproj[C_ * C_];
__device__ __half g_wt_tqkv [3 * C_ * C_];
__device__ __half g_wt_tproj[C_ * C_];
__device__ __half g_wt_fc1  [HID_ * C_];
__device__ __half g_wt_fc2  [C_ * HID_];

__device__ __forceinline__ uint32_t smem_u32(const void* p) {
    uint32_t a;
    asm("{ .reg .u64 t; cvta.to.shared.u64 t, %1; cvt.u32.u64 %0, t; }" : "=r"(a) : "l"(p));
    return a;
}
// e^(s-8) entirely on fma/alu pipes. Valid for s in [-40, 40].
__device__ __forceinline__ float fexp_shift(float s) {
    const float y = fmaf(s, 1.44269504089f, -11.5415603272f);
    const int   i = __float2int_rn(y);
    const float f = y - (float)i;
    float p = fmaf(f, 0.00133335581f, 0.00961812910f);
    p = fmaf(f, p, 0.0555041087f);
    p = fmaf(f, p, 0.240226507f);
    p = fmaf(f, p, 0.693147181f);
    p = fmaf(f, p, 1.0f);
    return __int_as_float(__float_as_int(p) + (i << 23));
}
__device__ __forceinline__ void ldsm4(uint32_t& r0, uint32_t& r1, uint32_t& r2,
                                      uint32_t& r3, uint32_t addr) {
    asm volatile("ldmatrix.sync.aligned.m8n8.x4.b16 {%0,%1,%2,%3}, [%4];"
        : "=r"(r0), "=r"(r1), "=r"(r2), "=r"(r3) : "r"(addr));
}
__device__ __forceinline__ void mma_f16(float c[4], const uint32_t a[4], const uint32_t b[2]) {
    asm volatile("mma.sync.aligned.m16n8k16.row.col.f32.f16.f16.f32 "
        "{%0,%1,%2,%3}, {%4,%5,%6,%7}, {%8,%9}, {%0,%1,%2,%3};"
        : "+f"(c[0]), "+f"(c[1]), "+f"(c[2]), "+f"(c[3])
        : "r"(a[0]), "r"(a[1]), "r"(a[2]), "r"(a[3]), "r"(b[0]), "r"(b[1]));
}
__device__ __forceinline__ uint32_t h2pack(float a, float b) {
    __half2 h = __floats2half2_rn(a, b);
    return *(uint32_t*)&h;
}

// ============================================================
// Fused weight transposes: all 6 weights in ONE launch.
// ============================================================
struct TWJob { const float* in; __half* out; int K; int N; int ntx; int base; };
struct TWPack { TWJob j[6]; };

__global__ void transpose_all(TWPack p)
{
    __shared__ float t[32][33];
    const int bt = blockIdx.x;
    int ji = 0;
    #pragma unroll
    for (int i = 1; i < 6; i++)
        if (bt >= p.j[i].base) ji = i;
    const TWJob& J = p.j[ji];
    const int lt = bt - J.base;
    const int n0 = (lt % J.ntx) * 32;
    const int k0 = (lt / J.ntx) * 32;
    const int x = threadIdx.x, y = threadIdx.y;
    #pragma unroll
    for (int i = 0; i < 32; i += 8)
        t[y + i][x] = J.in[(size_t)(k0 + y + i) * J.N + n0 + x];
    __syncthreads();
    #pragma unroll
    for (int i = 0; i < 32; i += 8)
        J.out[(size_t)(n0 + y + i) * J.K + k0 + x] = __float2half_rn(t[x][y + i]);
}

// ============================================================
// LayerNorm over C=1024 -> fp16, one warp per row (no barriers).
// PERM gathers through the (B,T,S)->(B,S,T) map.
// ============================================================
template<bool PERM>
__global__ void ln_kernel(const float* __restrict__ in, __half* __restrict__ out,
                          const float* __restrict__ w, const float* __restrict__ b)
{
    const int row  = blockIdx.x * 8 + (threadIdx.x >> 5);
    const int lane = threadIdx.x & 31;
    int in_row = row;
    if (PERM) {
        const int t = row & 15, s = (row >> 4) & 255, bb = row >> 12;
        in_row = bb * 4096 + t * 256 + s;
    }
    const float4* ip = reinterpret_cast<const float4*>(in + (size_t)in_row * 1024);

    float4 xv[8];
    float s = 0.f, ss = 0.f;
    #pragma unroll
    for (int i = 0; i < 8; i++) {
        xv[i] = ip[lane + 32 * i];
        s  += xv[i].x + xv[i].y + xv[i].z + xv[i].w;
        ss += xv[i].x*xv[i].x + xv[i].y*xv[i].y + xv[i].z*xv[i].z + xv[i].w*xv[i].w;
    }
    #pragma unroll
    for (int o = 16; o; o >>= 1) {
        s  += __shfl_xor_sync(0xffffffffu, s,  o);
        ss += __shfl_xor_sync(0xffffffffu, ss, o);
    }
    const float mean = s * (1.f / 1024.f);
    const float rstd = rsqrtf(ss * (1.f / 1024.f) - mean * mean + EPSF);

    const float4* wp = reinterpret_cast<const float4*>(w);
    const float4* bp = reinterpret_cast<const float4*>(b);
    uint2* op = reinterpret_cast<uint2*>(out + (size_t)row * 1024);
    #pragma unroll
    for (int i = 0; i < 8; i++) {
        const float4 wv = wp[lane + 32 * i];
        const float4 bv = bp[lane + 32 * i];
        uint2 pk;
        pk.x = h2pack((xv[i].x - mean) * rstd * wv.x + bv.x,
                      (xv[i].y - mean) * rstd * wv.y + bv.y);
        pk.y = h2pack((xv[i].z - mean) * rstd * wv.z + bv.z,
                      (xv[i].w - mean) * rstd * wv.w + bv.w);
        op[lane + 32 * i] = pk;
    }
}

// ============================================================
// Spatial attention, all-fp16 tensor cores.
// M-SPLIT: 2 CTAs per (batch,head), 128 query rows each ->
// regs < 128, smem 80KB -> 2 CTAs/SM.
// Q [128x128B] swz | K [256x128B] swz | Vt [64 d x 512B] swz.
// ============================================================
constexpr int ATTN_SMEM = 16384 + 32768 + 32768;   // 80 KB

__global__ __launch_bounds__(256, 2) void attn_tc(const __half* __restrict__ qkv,
                                                  __half* __restrict__ out)
{
    extern __shared__ float smf[];
    char* smc = (char*)smf;
    const uint32_t Qs = smem_u32(smf);
    const uint32_t Ks = Qs + 16384;
    const uint32_t Vt = Qs + 49152;

    const int tid = threadIdx.x, wid = tid >> 5, lane = tid & 31;
    const int g = lane >> 2, tig = lane & 3;
    const int bx = blockIdx.x;
    const int piece = bx & 1;
    const int bh = bx >> 1, h = bh & 15, batch = bh >> 4;
    const __half* base = qkv + (size_t)batch * 256 * 3072;

    // ---- stage Q (128 rows of this piece) ----
    #pragma unroll
    for (int t = 0; t < 4; t++) {
        const int idx = tid + (t << 8);          // 0..1023
        const int r = idx >> 3, c = idx & 7;     // local q row, 16B chunk
        const uint32_t dst = (uint32_t)(r * 128 + ((c ^ (r & 7)) << 4));
        const uint4 qv = *(const uint4*)(base + (size_t)(piece * 128 + r) * 3072 + h * 64 + c * 8);
        *(uint4*)(smc + dst) = qv;
    }
    // ---- stage K (full 256) and V (transposed, full 256) ----
    #pragma unroll
    for (int t = 0; t < 8; t++) {
        const int idx = tid + (t << 8);          // 0..2047
        const int r = idx >> 3, c = idx & 7;
        const uint32_t dst = (uint32_t)(r * 128 + ((c ^ (r & 7)) << 4));
        const uint4 kv = *(const uint4*)(base + (size_t)r * 3072 + 1024 + h * 64 + c * 8);
        *(uint4*)(smc + 16384 + dst) = kv;
        uint4 vv = *(const uint4*)(base + (size_t)r * 3072 + 2048 + h * 64 + c * 8);
        __half hv[8];
        *(uint4*)hv = vv;
        const int kc = r >> 3, kb = r & 7;
        #pragma unroll
        for (int i = 0; i < 8; i++) {
            const int d = c * 8 + i;
            const uint32_t vc = (uint32_t)((kc & 24) | ((kc ^ d) & 7));
            *(__half*)(smc + 49152 + d * 512 + (vc << 4) + kb * 2) = hv[i];
        }
    }
    __syncthreads();

    // ---- Q fragments (warp M-tile = 16 rows), resident ----
    const int lr = lane & 7;
    const int aRow = wid * 16 + ((lane >> 3) & 1) * 8 + lr;
    const int cbA = lane >> 4;
    uint32_t qf[4][4];
    #pragma unroll
    for (int ks = 0; ks < 4; ks++)
        ldsm4(qf[ks][0], qf[ks][1], qf[ks][2], qf[ks][3],
              Qs + (uint32_t)(aRow * 128) +
              (((uint32_t)(2 * ks + cbA) ^ (uint32_t)lr) << 4));

    const int bRow = (lane >> 4) * 8 + lr;
    const int cbB = (lane >> 3) & 1;

    float o[8][4];
    float rs[2] = {0.f, 0.f};
    #pragma unroll
    for (int no = 0; no < 8; no++)
        #pragma unroll
        for (int i = 0; i < 4; i++) o[no][i] = 0.f;

    for (int tile = 0; tile < 8; tile++) {
        // ---- S = Q @ K^T (32 keys) ----
        float s[4][4];
        #pragma unroll
        for (int nt = 0; nt < 4; nt++)
            #pragma unroll
            for (int i = 0; i < 4; i++) s[nt][i] = 0.f;
        #pragma unroll
        for (int ks = 0; ks < 4; ks++) {
            uint32_t kb_[4][2];
            #pragma unroll
            for (int ntp = 0; ntp < 2; ntp++)
                ldsm4(kb_[2*ntp][0], kb_[2*ntp][1], kb_[2*ntp+1][0], kb_[2*ntp+1][1],
                      Ks + (uint32_t)((tile * 32 + bRow + ntp * 16) * 128) +
                      (((uint32_t)(2 * ks + cbB) ^ (uint32_t)lr) << 4));
            #pragma unroll
            for (int nt = 0; nt < 4; nt++)
                mma_f16(s[nt], qf[ks], kb_[nt]);
        }
        // ---- softmax weights (fixed shift) + row-sum partials ----
        #pragma unroll
        for (int nt = 0; nt < 4; nt++)
            #pragma unroll
            for (int i = 0; i < 4; i++) {
                const float e = fexp_shift(s[nt][i]);
                rs[i >> 1] += e;
                s[nt][i] = e;
            }
        // ---- O += P @ V : A-fragments straight from S accumulators ----
        #pragma unroll
        for (int kk = 0; kk < 2; kk++) {
            uint32_t vb[8][2];
            const uint32_t c0 = (uint32_t)(tile * 4 + kk * 2 + cbB);
            #pragma unroll
            for (int ntp = 0; ntp < 4; ntp++) {
                const uint32_t row = (uint32_t)(bRow + ntp * 16);
                const uint32_t vc = (c0 & 24) | ((c0 ^ (uint32_t)lr) & 7);
                ldsm4(vb[2*ntp][0], vb[2*ntp][1], vb[2*ntp+1][0], vb[2*ntp+1][1],
                      Vt + row * 512 + (vc << 4));
            }
            uint32_t pa[4];
            pa[0] = h2pack(s[2*kk][0],   s[2*kk][1]);
            pa[1] = h2pack(s[2*kk][2],   s[2*kk][3]);
            pa[2] = h2pack(s[2*kk+1][0], s[2*kk+1][1]);
            pa[3] = h2pack(s[2*kk+1][2], s[2*kk+1][3]);
            #pragma unroll
            for (int no = 0; no < 8; no++)
                mma_f16(o[no], pa, vb[no]);
        }
    }

    // ---- normalize & write fp16 ----
    #pragma unroll
    for (int i = 0; i < 2; i++) {
        float v = rs[i];
        v += __shfl_xor_sync(0xffffffffu, v, 1);
        v += __shfl_xor_sync(0xffffffffu, v, 2);
        rs[i] = 1.f / v;
    }
    const int r0 = piece * 128 + wid * 16 + g;
    __half* p0 = out + ((size_t)batch * 256 + r0) * 1024 + h * 64;
    __half* p1 = p0 + 8 * 1024;
    #pragma unroll
    for (int no = 0; no < 8; no++) {
        *(uint32_t*)(p0 + no * 8 + tig * 2) =
            h2pack(o[no][0] * rs[0], o[no][1] * rs[0]);
        *(uint32_t*)(p1 + no * 8 + tig * 2) =
            h2pack(o[no][2] * rs[1], o[no][3] * rs[1]);
    }
}

// ============================================================
// Temporal attention (N=16), fp16 in/out, fp32 accumulate.
// ============================================================
__global__ void attn16_kernel(const __half* __restrict__ qkv, __half* __restrict__ out)
{
    constexpr int N = 16;
    const int tid = threadIdx.x;
    const int bh = blockIdx.x * 16 + (tid >> 4);
    const int h = bh & 15;
    const int batch = bh >> 4;
    const int row = tid & 15;
    const __half* base = qkv + (size_t)batch * N * 3072;

    __half2 q2[32];
    {
        const uint4* qp = reinterpret_cast<const uint4*>(base + (size_t)row * 3072 + h * 64);
        #pragma unroll
        for (int c = 0; c < 8; c++) *(uint4*)(q2 + c * 4) = qp[c];
    }

    float2 acc[32];
    #pragma unroll
    for (int d = 0; d < 32; d++) acc[d] = make_float2(0.f, 0.f);
    float sum = 0.f;
    #pragma unroll
    for (int j = 0; j < N; j++) {
        __half2 k2[32];
        const uint4* kp = reinterpret_cast<const uint4*>(base + (size_t)j * 3072 + 1024 + h * 64);
        #pragma unroll
        for (int c = 0; c < 8; c++) *(uint4*)(k2 + c * 4) = kp[c];
        float s = 0.f;
        #pragma unroll
        for (int d = 0; d < 32; d++) {
            const float2 qd = __half22float2(q2[d]);
            const float2 kd = __half22float2(k2[d]);
            s += qd.x * kd.x + qd.y * kd.y;
        }
        const float e = fexp_shift(s);
        sum += e;
        __half2 v2[32];
        const uint4* vp = reinterpret_cast<const uint4*>(base + (size_t)j * 3072 + 2048 + h * 64);
        #pragma unroll
        for (int c = 0; c < 8; c++) *(uint4*)(v2 + c * 4) = vp[c];
        #pragma unroll
        for (int d = 0; d < 32; d++) {
            const float2 vd = __half22float2(v2[d]);
            acc[d].x += e * vd.x;
            acc[d].y += e * vd.y;
        }
    }
    const float inv = 1.f / sum;
    uint32_t* op = reinterpret_cast<uint32_t*>(out + ((size_t)batch * N + row) * 1024 + h * 64);
    #pragma unroll
    for (int d = 0; d < 32; d++)
        op[d] = h2pack(acc[d].x * inv, acc[d].y * inv);
}

// ============================================================
// fp16 tensor-core GEMM: 128x128 block, 32x64 warp tiles,
// THREE-stage cp.async pipeline, one barrier per K-iteration.
//   C[M,N] = A[M,K] @ Bt[N,K]^T  (+bias)(+resid)(+gelu)
// QKVLN: per-head LN of q,k fused into epilogue.
// ============================================================
constexpr int STG_B    = 32768;           // A 16KB + B 16KB
constexpr int GEMM_SMEM = 3 * STG_B;      // 96 KB

template<bool GELU, bool HALFOUT, bool PERMROW, bool QKVLN>
__global__ __launch_bounds__(256, 2) void gemm_mma(
    const __half* __restrict__ A, const __half* __restrict__ Bt,
    void* __restrict__ Cv, const float* __restrict__ bias,
    const float* __restrict__ resid, int M, int N, int K,
    const float* __restrict__ hn_w, const float* __restrict__ hn_b, float qscale)
{
    extern __shared__ float sm[];
    const uint32_t stg = smem_u32(sm);

    const int tid = threadIdx.x;
    const int wid = tid >> 5, lane = tid & 31;
    const int g = lane >> 2, tig = lane & 3;
    const int warpM = wid & 3, warpN = wid >> 2;
    const int bx = blockIdx.x, by = blockIdx.y;
    const int NKB = K >> 6;

    uint32_t a_s[4], b_s[4];
    const __half *a_g[4], *b_g[4];
    #pragma unroll
    for (int t = 0; t < 4; t++) {
        const int idx = tid + (t << 8);
        const int r = idx >> 3, c = idx & 7;
        const uint32_t sw = (uint32_t)(r * 128 + ((c ^ (r & 7)) << 4));
        a_s[t] = sw;            b_s[t] = sw + 16384;
        a_g[t] = A  + (size_t)(by * 128 + r) * K + c * 8;
        b_g[t] = Bt + (size_t)(bx * 128 + r) * K + c * 8;
    }

    auto load_stage = [&](int s, int kb) {
        const uint32_t sb = stg + s * STG_B;
        const int ko = kb << 6;
        #pragma unroll
        for (int t = 0; t < 4; t++)
            asm volatile("cp.async.cg.shared.global [%0], [%1], 16;" ::
                "r"(sb + a_s[t]), "l"(a_g[t] + ko) : "memory");
        #pragma unroll
        for (int t = 0; t < 4; t++)
            asm volatile("cp.async.cg.shared.global [%0], [%1], 16;" ::
                "r"(sb + b_s[t]), "l"(b_g[t] + ko) : "memory");
    };

    const int lr = lane & 7;
    const int aRow = warpM * 32 + ((lane >> 3) & 1) * 8 + lr;
    const int cbA  = lane >> 4;
    const uint32_t aRx = (uint32_t)(aRow * 128);
    const uint32_t a7  = (uint32_t)(aRow & 7);
    const int bRow = warpN * 64 + (lane >> 4) * 8 + lr;
    const int cbB  = (lane >> 3) & 1;
    const uint32_t bRx = (uint32_t)(bRow * 128);
    const uint32_t b7  = (uint32_t)(bRow & 7);

    float acc[2][8][4];
    #pragma unroll
    for (int mt = 0; mt < 2; mt++)
        #pragma unroll
        for (int nt = 0; nt < 8; nt++)
            #pragma unroll
            for (int i = 0; i < 4; i++) acc[mt][nt][i] = 0.f;

    load_stage(0, 0);
    asm volatile("cp.async.commit_group;" ::: "memory");
    load_stage(1, 1);
    asm volatile("cp.async.commit_group;" ::: "memory");

    int sidx = 0;
    for (int kb = 0; kb < NKB; kb++) {
        if (kb < NKB - 1) {
            asm volatile("cp.async.wait_group 1;" ::: "memory");
        } else {
            asm volatile("cp.async.wait_group 0;" ::: "memory");
        }
        __syncthreads();

        const uint32_t sA = stg + sidx * STG_B;
        const uint32_t sB = sA + 16384;
        #pragma unroll
        for (int ks = 0; ks < 4; ks++) {
            uint32_t a[2][4], b[8][2];
            const uint32_t swA = ((uint32_t)(2 * ks + cbA) ^ a7) << 4;
            #pragma unroll
            for (int mt = 0; mt < 2; mt++)
                ldsm4(a[mt][0], a[mt][1], a[mt][2], a[mt][3],
                      sA + aRx + (uint32_t)(mt * 16 * 128) + swA);
            const uint32_t swB = ((uint32_t)(2 * ks + cbB) ^ b7) << 4;
            #pragma unroll
            for (int ntp = 0; ntp < 4; ntp++)
                ldsm4(b[2 * ntp][0], b[2 * ntp][1], b[2 * ntp + 1][0], b[2 * ntp + 1][1],
                      sB + bRx + (uint32_t)(ntp * 16 * 128) + swB);
            #pragma unroll
            for (int mt = 0; mt < 2; mt++)
                #pragma unroll
                for (int nt = 0; nt < 8; nt++)
                    mma_f16(acc[mt][nt], a[mt], b[nt]);
        }

        if (kb + 2 < NKB) {
            const int s2 = (sidx + 2 >= 3) ? sidx - 1 : sidx + 2;
            load_stage(s2, kb + 2);
            asm volatile("cp.async.commit_group;" ::: "memory");
        } else {
            asm volatile("cp.async.commit_group;" ::: "memory");
        }
        sidx = (sidx + 1 == 3) ? 0 : sidx + 1;
    }

    // ---- epilogue ----
    const int colblk = bx * 128 + warpN * 64;
    const int which = QKVLN ? (colblk >> 10) : 2;   // 0 q, 1 k, 2 v
    const float lnscale = (which == 0) ? qscale : 1.f;

    #pragma unroll
    for (int mt = 0; mt < 2; mt++) {
        #pragma unroll
        for (int half = 0; half < 2; half++) {
            int row = by * 128 + warpM * 32 + mt * 16 + g + half * 8;
            if (PERMROW) {
                const int t = row & 15, s = (row >> 4) & 255, bb = row >> 12;
                row = bb * 4096 + t * 256 + s;
            }
            float mean = 0.f, rstd = 1.f;
            if (QKVLN && which < 2) {
                float s1 = 0.f, s2 = 0.f;
                #pragma unroll
                for (int nt = 0; nt < 8; nt++) {
                    const float u0 = acc[mt][nt][half * 2 + 0];
                    const float u1 = acc[mt][nt][half * 2 + 1];
                    s1 += u0 + u1;
                    s2 += u0 * u0 + u1 * u1;
                }
                s1 += __shfl_xor_sync(0xffffffffu, s1, 1);
                s2 += __shfl_xor_sync(0xffffffffu, s2, 1);
                s1 += __shfl_xor_sync(0xffffffffu, s1, 2);
                s2 += __shfl_xor_sync(0xffffffffu, s2, 2);
                mean = s1 * (1.f / 64.f);
                rstd = rsqrtf(s2 * (1.f / 64.f) - mean * mean + EPSF);
            }
            const float* rp = resid ? resid + (size_t)row * N : nullptr;
            #pragma unroll
            for (int nt = 0; nt < 8; nt++) {
                const int col = colblk + nt * 8 + tig * 2;
                float v0 = acc[mt][nt][half * 2 + 0];
                float v1 = acc[mt][nt][half * 2 + 1];
                if (QKVLN) {
                    if (which < 2) {
                        const int hc = nt * 8 + tig * 2;
                        v0 = ((v0 - mean) * rstd * hn_w[hc]     + hn_b[hc])     * lnscale;
                        v1 = ((v1 - mean) * rstd * hn_w[hc + 1] + hn_b[hc + 1]) * lnscale;
                    }
                } else {
                    if (bias) { v0 += bias[col]; v1 += bias[col + 1]; }
                    if (rp)   { v0 += rp[col];   v1 += rp[col + 1]; }
                    if (GELU) {
                        v0 = 0.5f * v0 * (1.f + erff(v0 * 0.70710678f));
                        v1 = 0.5f * v1 * (1.f + erff(v1 * 0.70710678f));
                    }
                }
                if (HALFOUT) {
                    __half* cp = (__half*)Cv + (size_t)row * N + col;
                    *(uint32_t*)cp = h2pack(v0, v1);
                } else {
                    float* cp = (float*)Cv + (size_t)row * N + col;
                    float2 v; v.x = v0; v.y = v1;
                    *(float2*)cp = v;
                }
            }
        }
    }
}

// ============================================================
extern "C" void kernel_launch(void* const* d_in, const int* /*in_sizes*/, int /*n_in*/,
                              void* d_out, int /*out_size*/)
{
    const float* x        = (const float*)d_in[0];
    const float* ns_w     = (const float*)d_in[1];
    const float* ns_b     = (const float*)d_in[2];
    const float* nt_w     = (const float*)d_in[3];
    const float* nt_b     = (const float*)d_in[4];
    const float* nm_w     = (const float*)d_in[5];
    const float* nm_b     = (const float*)d_in[6];
    const float* s_qkv    = (const float*)d_in[7];
    const float* s_qkn_w  = (const float*)d_in[8];
    const float* s_qkn_b  = (const float*)d_in[9];
    const float* s_proj_w = (const float*)d_in[10];
    const float* s_proj_b = (const float*)d_in[11];
    const float* t_qkv    = (const float*)d_in[12];
    const float* t_qkn_w  = (const float*)d_in[13];
    const float* t_qkn_b  = (const float*)d_in[14];
    const float* t_proj_w = (const float*)d_in[15];
    const float* t_proj_b = (const float*)d_in[16];
    const float* fc1_w    = (const float*)d_in[17];
    const float* fc1_b    = (const float*)d_in[18];
    const float* fc2_w    = (const float*)d_in[19];
    const float* fc2_b    = (const float*)d_in[20];
    float* out = (float*)d_out;

    float *xbuf;
    __half *xln, *qkv, *attn, *hbuf;
    __half *wt_sqkv, *wt_sproj, *wt_tqkv, *wt_tproj, *wt_fc1, *wt_fc2;
    cudaGetSymbolAddress((void**)&xbuf, g_xbuf);
    cudaGetSymbolAddress((void**)&xln,  g_xln);
    cudaGetSymbolAddress((void**)&qkv,  g_qkv);
    cudaGetSymbolAddress((void**)&attn, g_attn);
    cudaGetSymbolAddress((void**)&hbuf, g_h);
    cudaGetSymbolAddress((void**)&wt_sqkv,  g_wt_sqkv);
    cudaGetSymbolAddress((void**)&wt_sproj, g_wt_sproj);
    cudaGetSymbolAddress((void**)&wt_tqkv,  g_wt_tqkv);
    cudaGetSymbolAddress((void**)&wt_tproj, g_wt_tproj);
    cudaGetSymbolAddress((void**)&wt_fc1,   g_wt_fc1);
    cudaGetSymbolAddress((void**)&wt_fc2,   g_wt_fc2);

    cudaFuncSetAttribute(attn_tc, cudaFuncAttributeMaxDynamicSharedMemorySize, ATTN_SMEM);
    cudaFuncSetAttribute((const void*)gemm_mma<false, false, false, false>,
                         cudaFuncAttributeMaxDynamicSharedMemorySize, GEMM_SMEM);
    cudaFuncSetAttribute((const void*)gemm_mma<false, true,  false, true>,
                         cudaFuncAttributeMaxDynamicSharedMemorySize, GEMM_SMEM);
    cudaFuncSetAttribute((const void*)gemm_mma<false, false, true,  false>,
                         cudaFuncAttributeMaxDynamicSharedMemorySize, GEMM_SMEM);
    cudaFuncSetAttribute((const void*)gemm_mma<true,  true,  false, false>,
                         cudaFuncAttributeMaxDynamicSharedMemorySize, GEMM_SMEM);

    // ---- all 6 weight transposes (+ fp16 rounding) in one launch ----
    TWPack pk;
    int base = 0;
    auto mk = [&](const float* in, __half* o, int K, int N) {
        TWJob j; j.in = in; j.out = o; j.K = K; j.N = N; j.ntx = N / 32; j.base = base;
        base += (N / 32) * (K / 32);
        return j;
    };
    pk.j[0] = mk(s_qkv,    wt_sqkv,  1024, 3072);
    pk.j[1] = mk(s_proj_w, wt_sproj, 1024, 1024);
    pk.j[2] = mk(t_qkv,    wt_tqkv,  1024, 3072);
    pk.j[3] = mk(t_proj_w, wt_tproj, 1024, 1024);
    pk.j[4] = mk(fc1_w,    wt_fc1,   1024, 4096);
    pk.j[5] = mk(fc2_w,    wt_fc2,   4096, 1024);
    transpose_all<<<base, dim3(32, 8)>>>(pk);

    // ---- spatial attention block ----
    ln_kernel<false><<<R_ / 8, 256>>>(x, xln, ns_w, ns_b);
    gemm_mma<false, true, false, true><<<dim3(24, 64), 256, GEMM_SMEM>>>(
        xln, wt_sqkv, qkv, nullptr, nullptr, R_, 3072, 1024, s_qkn_w, s_qkn_b, SCALE_);
    attn_tc<<<B_ * T_ * H_ * 2, 256, ATTN_SMEM>>>(qkv, attn);
    gemm_mma<false, false, false, false><<<dim3(8, 64), 256, GEMM_SMEM>>>(
        attn, wt_sproj, xbuf, s_proj_b, x, R_, 1024, 1024, nullptr, nullptr, 1.f);

    // ---- temporal attention block (permutes fused into ln + gemm) ----
    ln_kernel<true><<<R_ / 8, 256>>>(xbuf, xln, nt_w, nt_b);
    gemm_mma<false, true, false, true><<<dim3(24, 64), 256, GEMM_SMEM>>>(
        xln, wt_tqkv, qkv, nullptr, nullptr, R_, 3072, 1024, t_qkn_w, t_qkn_b, SCALE_);
    attn16_kernel<<<(B_ * S_ * H_) / 16, 256>>>(qkv, attn);
    gemm_mma<false, false, true, false><<<dim3(8, 64), 256, GEMM_SMEM>>>(
        attn, wt_tproj, xbuf, t_proj_b, xbuf, R_, 1024, 1024, nullptr, nullptr, 1.f);

    // ---- MLP ----
    ln_kernel<false><<<R_ / 8, 256>>>(xbuf, xln, nm_w, nm_b);
    gemm_mma<true,  true,  false, false><<<dim3(32, 64), 256, GEMM_SMEM>>>(
        xln, wt_fc1, hbuf, fc1_b, nullptr, R_, 4096, 1024, nullptr, nullptr, 1.f);
    gemm_mma<false, false, false, false><<<dim3(8, 64), 256, GEMM_SMEM>>>(
        hbuf, wt_fc2, out, fc2_b, xbuf, R_, 1024, 4096, nullptr, nullptr, 1.f);
}

// round 17
// speedup vs baseline: 1.0246x; 1.0061x over previous
#include <cuda_runtime.h>
#include <cuda_fp16.h>
#include <cstdint>
#include <math.h>

#define EPSF 1e-5f

constexpr int B_  = 2, T_ = 16, S_ = 256, C_ = 1024, H_ = 16;
constexpr int R_  = B_ * T_ * S_;   // 8192 tokens
constexpr int HID_ = 4 * C_;        // 4096
constexpr float SCALE_ = 8.0f / 64.0f;

// ---- scratch (device globals; no runtime allocation allowed) ----
__device__ __half g_xbuf[R_ * C_];     // residual trunk, now fp16
__device__ __half g_xln [R_ * C_];
__device__ __half g_qkv [R_ * 3 * C_];
__device__ __half g_attn[R_ * C_];
__device__ __half g_h   [R_ * HID_];
// transposed (fp16) weights, [N,K] row-major
__device__ __half g_wt_sqkv [3 * C_ * C_];
__device__ __half g_wt_sproj[C_ * C_];
__device__ __half g_wt_tqkv [3 * C_ * C_];
__device__ __half g_wt_tproj[C_ * C_];
__device__ __half g_wt_fc1  [HID_ * C_];
__device__ __half g_wt_fc2  [C_ * HID_];

__device__ __forceinline__ uint32_t smem_u32(const void* p) {
    uint32_t a;
    asm("{ .reg .u64 t; cvta.to.shared.u64 t, %1; cvt.u32.u64 %0, t; }" : "=r"(a) : "l"(p));
    return a;
}
// e^(s-8) entirely on fma/alu pipes. Valid for s in [-40, 40].
__device__ __forceinline__ float fexp_shift(float s) {
    const float y = fmaf(s, 1.44269504089f, -11.5415603272f);
    const int   i = __float2int_rn(y);
    const float f = y - (float)i;
    float p = fmaf(f, 0.00133335581f, 0.00961812910f);
    p = fmaf(f, p, 0.0555041087f);
    p = fmaf(f, p, 0.240226507f);
    p = fmaf(f, p, 0.693147181f);
    p = fmaf(f, p, 1.0f);
    return __int_as_float(__float_as_int(p) + (i << 23));
}
__device__ __forceinline__ void ldsm4(uint32_t& r0, uint32_t& r1, uint32_t& r2,
                                      uint32_t& r3, uint32_t addr) {
    asm volatile("ldmatrix.sync.aligned.m8n8.x4.b16 {%0,%1,%2,%3}, [%4];"
        : "=r"(r0), "=r"(r1), "=r"(r2), "=r"(r3) : "r"(addr));
}
__device__ __forceinline__ void mma_f16(float c[4], const uint32_t a[4], const uint32_t b[2]) {
    asm volatile("mma.sync.aligned.m16n8k16.row.col.f32.f16.f16.f32 "
        "{%0,%1,%2,%3}, {%4,%5,%6,%7}, {%8,%9}, {%0,%1,%2,%3};"
        : "+f"(c[0]), "+f"(c[1]), "+f"(c[2]), "+f"(c[3])
        : "r"(a[0]), "r"(a[1]), "r"(a[2]), "r"(a[3]), "r"(b[0]), "r"(b[1]));
}
__device__ __forceinline__ uint32_t h2pack(float a, float b) {
    __half2 h = __floats2half2_rn(a, b);
    return *(uint32_t*)&h;
}

// ============================================================
// Fused weight transposes: all 6 weights in ONE launch.
// ============================================================
struct TWJob { const float* in; __half* out; int K; int N; int ntx; int base; };
struct TWPack { TWJob j[6]; };

__global__ void transpose_all(TWPack p)
{
    __shared__ float t[32][33];
    const int bt = blockIdx.x;
    int ji = 0;
    #pragma unroll
    for (int i = 1; i < 6; i++)
        if (bt >= p.j[i].base) ji = i;
    const TWJob& J = p.j[ji];
    const int lt = bt - J.base;
    const int n0 = (lt % J.ntx) * 32;
    const int k0 = (lt / J.ntx) * 32;
    const int x = threadIdx.x, y = threadIdx.y;
    #pragma unroll
    for (int i = 0; i < 32; i += 8)
        t[y + i][x] = J.in[(size_t)(k0 + y + i) * J.N + n0 + x];
    __syncthreads();
    #pragma unroll
    for (int i = 0; i < 32; i += 8)
        J.out[(size_t)(n0 + y + i) * J.K + k0 + x] = __float2half_rn(t[x][y + i]);
}

// ============================================================
// LayerNorm (fp32 input) -> fp16, one warp per row. For x only.
// ============================================================
__global__ void ln_kernel(const float* __restrict__ in, __half* __restrict__ out,
                          const float* __restrict__ w, const float* __restrict__ b)
{
    const int row  = blockIdx.x * 8 + (threadIdx.x >> 5);
    const int lane = threadIdx.x & 31;
    const float4* ip = reinterpret_cast<const float4*>(in + (size_t)row * 1024);

    float4 xv[8];
    float s = 0.f, ss = 0.f;
    #pragma unroll
    for (int i = 0; i < 8; i++) {
        xv[i] = ip[lane + 32 * i];
        s  += xv[i].x + xv[i].y + xv[i].z + xv[i].w;
        ss += xv[i].x*xv[i].x + xv[i].y*xv[i].y + xv[i].z*xv[i].z + xv[i].w*xv[i].w;
    }
    #pragma unroll
    for (int o = 16; o; o >>= 1) {
        s  += __shfl_xor_sync(0xffffffffu, s,  o);
        ss += __shfl_xor_sync(0xffffffffu, ss, o);
    }
    const float mean = s * (1.f / 1024.f);
    const float rstd = rsqrtf(ss * (1.f / 1024.f) - mean * mean + EPSF);

    const float4* wp = reinterpret_cast<const float4*>(w);
    const float4* bp = reinterpret_cast<const float4*>(b);
    uint2* op = reinterpret_cast<uint2*>(out + (size_t)row * 1024);
    #pragma unroll
    for (int i = 0; i < 8; i++) {
        const float4 wv = wp[lane + 32 * i];
        const float4 bv = bp[lane + 32 * i];
        uint2 pk;
        pk.x = h2pack((xv[i].x - mean) * rstd * wv.x + bv.x,
                      (xv[i].y - mean) * rstd * wv.y + bv.y);
        pk.y = h2pack((xv[i].z - mean) * rstd * wv.z + bv.z,
                      (xv[i].w - mean) * rstd * wv.w + bv.w);
        op[lane + 32 * i] = pk;
    }
}

// ============================================================
// LayerNorm (fp16 input) -> fp16, one warp per row.
// PERM gathers through the (B,T,S)->(B,S,T) map. For xbuf.
// ============================================================
template<bool PERM>
__global__ void ln_h_kernel(const __half* __restrict__ in, __half* __restrict__ out,
                            const float* __restrict__ w, const float* __restrict__ b)
{
    const int row  = blockIdx.x * 8 + (threadIdx.x >> 5);
    const int lane = threadIdx.x & 31;
    int in_row = row;
    if (PERM) {
        const int t = row & 15, s = (row >> 4) & 255, bb = row >> 12;
        in_row = bb * 4096 + t * 256 + s;
    }
    const uint4* ip = reinterpret_cast<const uint4*>(in + (size_t)in_row * 1024);

    __half2 hv[16];
    float s = 0.f, ss = 0.f;
    #pragma unroll
    for (int i = 0; i < 4; i++) {
        const uint4 v = ip[lane + 32 * i];
        *(uint4*)(hv + i * 4) = v;
        #pragma unroll
        for (int k = 0; k < 4; k++) {
            const float2 f = __half22float2(hv[i * 4 + k]);
            s  += f.x + f.y;
            ss += f.x * f.x + f.y * f.y;
        }
    }
    #pragma unroll
    for (int o = 16; o; o >>= 1) {
        s  += __shfl_xor_sync(0xffffffffu, s,  o);
        ss += __shfl_xor_sync(0xffffffffu, ss, o);
    }
    const float mean = s * (1.f / 1024.f);
    const float rstd = rsqrtf(ss * (1.f / 1024.f) - mean * mean + EPSF);

    const float4* wp = reinterpret_cast<const float4*>(w);
    const float4* bp = reinterpret_cast<const float4*>(b);
    uint4* op = reinterpret_cast<uint4*>(out + (size_t)row * 1024);
    #pragma unroll
    for (int i = 0; i < 4; i++) {
        const int j = lane + 32 * i;       // uint4 chunk = elements 8j..8j+7
        uint32_t pk[4];
        #pragma unroll
        for (int k = 0; k < 2; k++) {
            const float4 wv = wp[2 * j + k];
            const float4 bv = bp[2 * j + k];
            const float2 f0 = __half22float2(hv[i * 4 + 2 * k + 0]);
            const float2 f1 = __half22float2(hv[i * 4 + 2 * k + 1]);
            pk[2 * k + 0] = h2pack((f0.x - mean) * rstd * wv.x + bv.x,
                                   (f0.y - mean) * rstd * wv.y + bv.y);
            pk[2 * k + 1] = h2pack((f1.x - mean) * rstd * wv.z + bv.z,
                                   (f1.y - mean) * rstd * wv.w + bv.w);
        }
        uint4 o4; o4.x = pk[0]; o4.y = pk[1]; o4.z = pk[2]; o4.w = pk[3];
        op[j] = o4;
    }
}

// ============================================================
// Spatial attention, all-fp16 tensor cores (unchanged R16).
// ============================================================
constexpr int ATTN_SMEM = 16384 + 32768 + 32768;   // 80 KB

__global__ __launch_bounds__(256, 2) void attn_tc(const __half* __restrict__ qkv,
                                                  __half* __restrict__ out)
{
    extern __shared__ float smf[];
    char* smc = (char*)smf;
    const uint32_t Qs = smem_u32(smf);
    const uint32_t Ks = Qs + 16384;
    const uint32_t Vt = Qs + 49152;

    const int tid = threadIdx.x, wid = tid >> 5, lane = tid & 31;
    const int g = lane >> 2, tig = lane & 3;
    const int bx = blockIdx.x;
    const int piece = bx & 1;
    const int bh = bx >> 1, h = bh & 15, batch = bh >> 4;
    const __half* base = qkv + (size_t)batch * 256 * 3072;

    #pragma unroll
    for (int t = 0; t < 4; t++) {
        const int idx = tid + (t << 8);
        const int r = idx >> 3, c = idx & 7;
        const uint32_t dst = (uint32_t)(r * 128 + ((c ^ (r & 7)) << 4));
        const uint4 qv = *(const uint4*)(base + (size_t)(piece * 128 + r) * 3072 + h * 64 + c * 8);
        *(uint4*)(smc + dst) = qv;
    }
    #pragma unroll
    for (int t = 0; t < 8; t++) {
        const int idx = tid + (t << 8);
        const int r = idx >> 3, c = idx & 7;
        const uint32_t dst = (uint32_t)(r * 128 + ((c ^ (r & 7)) << 4));
        const uint4 kv = *(const uint4*)(base + (size_t)r * 3072 + 1024 + h * 64 + c * 8);
        *(uint4*)(smc + 16384 + dst) = kv;
        uint4 vv = *(const uint4*)(base + (size_t)r * 3072 + 2048 + h * 64 + c * 8);
        __half hv[8];
        *(uint4*)hv = vv;
        const int kc = r >> 3, kb = r & 7;
        #pragma unroll
        for (int i = 0; i < 8; i++) {
            const int d = c * 8 + i;
            const uint32_t vc = (uint32_t)((kc & 24) | ((kc ^ d) & 7));
            *(__half*)(smc + 49152 + d * 512 + (vc << 4) + kb * 2) = hv[i];
        }
    }
    __syncthreads();

    const int lr = lane & 7;
    const int aRow = wid * 16 + ((lane >> 3) & 1) * 8 + lr;
    const int cbA = lane >> 4;
    uint32_t qf[4][4];
    #pragma unroll
    for (int ks = 0; ks < 4; ks++)
        ldsm4(qf[ks][0], qf[ks][1], qf[ks][2], qf[ks][3],
              Qs + (uint32_t)(aRow * 128) +
              (((uint32_t)(2 * ks + cbA) ^ (uint32_t)lr) << 4));

    const int bRow = (lane >> 4) * 8 + lr;
    const int cbB = (lane >> 3) & 1;

    float o[8][4];
    float rs[2] = {0.f, 0.f};
    #pragma unroll
    for (int no = 0; no < 8; no++)
        #pragma unroll
        for (int i = 0; i < 4; i++) o[no][i] = 0.f;

    for (int tile = 0; tile < 8; tile++) {
        float s[4][4];
        #pragma unroll
        for (int nt = 0; nt < 4; nt++)
            #pragma unroll
            for (int i = 0; i < 4; i++) s[nt][i] = 0.f;
        #pragma unroll
        for (int ks = 0; ks < 4; ks++) {
            uint32_t kb_[4][2];
            #pragma unroll
            for (int ntp = 0; ntp < 2; ntp++)
                ldsm4(kb_[2*ntp][0], kb_[2*ntp][1], kb_[2*ntp+1][0], kb_[2*ntp+1][1],
                      Ks + (uint32_t)((tile * 32 + bRow + ntp * 16) * 128) +
                      (((uint32_t)(2 * ks + cbB) ^ (uint32_t)lr) << 4));
            #pragma unroll
            for (int nt = 0; nt < 4; nt++)
                mma_f16(s[nt], qf[ks], kb_[nt]);
        }
        #pragma unroll
        for (int nt = 0; nt < 4; nt++)
            #pragma unroll
            for (int i = 0; i < 4; i++) {
                const float e = fexp_shift(s[nt][i]);
                rs[i >> 1] += e;
                s[nt][i] = e;
            }
        #pragma unroll
        for (int kk = 0; kk < 2; kk++) {
            uint32_t vb[8][2];
            const uint32_t c0 = (uint32_t)(tile * 4 + kk * 2 + cbB);
            #pragma unroll
            for (int ntp = 0; ntp < 4; ntp++) {
                const uint32_t row = (uint32_t)(bRow + ntp * 16);
                const uint32_t vc = (c0 & 24) | ((c0 ^ (uint32_t)lr) & 7);
                ldsm4(vb[2*ntp][0], vb[2*ntp][1], vb[2*ntp+1][0], vb[2*ntp+1][1],
                      Vt + row * 512 + (vc << 4));
            }
            uint32_t pa[4];
            pa[0] = h2pack(s[2*kk][0],   s[2*kk][1]);
            pa[1] = h2pack(s[2*kk][2],   s[2*kk][3]);
            pa[2] = h2pack(s[2*kk+1][0], s[2*kk+1][1]);
            pa[3] = h2pack(s[2*kk+1][2], s[2*kk+1][3]);
            #pragma unroll
            for (int no = 0; no < 8; no++)
                mma_f16(o[no], pa, vb[no]);
        }
    }

    #pragma unroll
    for (int i = 0; i < 2; i++) {
        float v = rs[i];
        v += __shfl_xor_sync(0xffffffffu, v, 1);
        v += __shfl_xor_sync(0xffffffffu, v, 2);
        rs[i] = 1.f / v;
    }
    const int r0 = piece * 128 + wid * 16 + g;
    __half* p0 = out + ((size_t)batch * 256 + r0) * 1024 + h * 64;
    __half* p1 = p0 + 8 * 1024;
    #pragma unroll
    for (int no = 0; no < 8; no++) {
        *(uint32_t*)(p0 + no * 8 + tig * 2) =
            h2pack(o[no][0] * rs[0], o[no][1] * rs[0]);
        *(uint32_t*)(p1 + no * 8 + tig * 2) =
            h2pack(o[no][2] * rs[1], o[no][3] * rs[1]);
    }
}

// ============================================================
// Temporal attention (N=16), fp16 in/out, fp32 accumulate.
// ============================================================
__global__ void attn16_kernel(const __half* __restrict__ qkv, __half* __restrict__ out)
{
    constexpr int N = 16;
    const int tid = threadIdx.x;
    const int bh = blockIdx.x * 16 + (tid >> 4);
    const int h = bh & 15;
    const int batch = bh >> 4;
    const int row = tid & 15;
    const __half* base = qkv + (size_t)batch * N * 3072;

    __half2 q2[32];
    {
        const uint4* qp = reinterpret_cast<const uint4*>(base + (size_t)row * 3072 + h * 64);
        #pragma unroll
        for (int c = 0; c < 8; c++) *(uint4*)(q2 + c * 4) = qp[c];
    }

    float2 acc[32];
    #pragma unroll
    for (int d = 0; d < 32; d++) acc[d] = make_float2(0.f, 0.f);
    float sum = 0.f;
    #pragma unroll
    for (int j = 0; j < N; j++) {
        __half2 k2[32];
        const uint4* kp = reinterpret_cast<const uint4*>(base + (size_t)j * 3072 + 1024 + h * 64);
        #pragma unroll
        for (int c = 0; c < 8; c++) *(uint4*)(k2 + c * 4) = kp[c];
        float s = 0.f;
        #pragma unroll
        for (int d = 0; d < 32; d++) {
            const float2 qd = __half22float2(q2[d]);
            const float2 kd = __half22float2(k2[d]);
            s += qd.x * kd.x + qd.y * kd.y;
        }
        const float e = fexp_shift(s);
        sum += e;
        __half2 v2[32];
        const uint4* vp = reinterpret_cast<const uint4*>(base + (size_t)j * 3072 + 2048 + h * 64);
        #pragma unroll
        for (int c = 0; c < 8; c++) *(uint4*)(v2 + c * 4) = vp[c];
        #pragma unroll
        for (int d = 0; d < 32; d++) {
            const float2 vd = __half22float2(v2[d]);
            acc[d].x += e * vd.x;
            acc[d].y += e * vd.y;
        }
    }
    const float inv = 1.f / sum;
    uint32_t* op = reinterpret_cast<uint32_t*>(out + ((size_t)batch * N + row) * 1024 + h * 64);
    #pragma unroll
    for (int d = 0; d < 32; d++)
        op[d] = h2pack(acc[d].x * inv, acc[d].y * inv);
}

// ============================================================
// fp16 tensor-core GEMM (R16 mainloop; epilogue adds RESH for
// fp16 residual reads).
// ============================================================
constexpr int STG_B    = 32768;           // A 16KB + B 16KB
constexpr int GEMM_SMEM = 3 * STG_B;      // 96 KB

template<bool GELU, bool HALFOUT, bool PERMROW, bool QKVLN, bool RESH>
__global__ __launch_bounds__(256, 2) void gemm_mma(
    const __half* __restrict__ A, const __half* __restrict__ Bt,
    void* __restrict__ Cv, const float* __restrict__ bias,
    const void* __restrict__ residv, int M, int N, int K,
    const float* __restrict__ hn_w, const float* __restrict__ hn_b, float qscale)
{
    extern __shared__ float sm[];
    const uint32_t stg = smem_u32(sm);

    const int tid = threadIdx.x;
    const int wid = tid >> 5, lane = tid & 31;
    const int g = lane >> 2, tig = lane & 3;
    const int warpM = wid & 3, warpN = wid >> 2;
    const int bx = blockIdx.x, by = blockIdx.y;
    const int NKB = K >> 6;

    uint32_t a_s[4], b_s[4];
    const __half *a_g[4], *b_g[4];
    #pragma unroll
    for (int t = 0; t < 4; t++) {
        const int idx = tid + (t << 8);
        const int r = idx >> 3, c = idx & 7;
        const uint32_t sw = (uint32_t)(r * 128 + ((c ^ (r & 7)) << 4));
        a_s[t] = sw;            b_s[t] = sw + 16384;
        a_g[t] = A  + (size_t)(by * 128 + r) * K + c * 8;
        b_g[t] = Bt + (size_t)(bx * 128 + r) * K + c * 8;
    }

    auto load_stage = [&](int s, int kb) {
        const uint32_t sb = stg + s * STG_B;
        const int ko = kb << 6;
        #pragma unroll
        for (int t = 0; t < 4; t++)
            asm volatile("cp.async.cg.shared.global [%0], [%1], 16;" ::
                "r"(sb + a_s[t]), "l"(a_g[t] + ko) : "memory");
        #pragma unroll
        for (int t = 0; t < 4; t++)
            asm volatile("cp.async.cg.shared.global [%0], [%1], 16;" ::
                "r"(sb + b_s[t]), "l"(b_g[t] + ko) : "memory");
    };

    const int lr = lane & 7;
    const int aRow = warpM * 32 + ((lane >> 3) & 1) * 8 + lr;
    const int cbA  = lane >> 4;
    const uint32_t aRx = (uint32_t)(aRow * 128);
    const uint32_t a7  = (uint32_t)(aRow & 7);
    const int bRow = warpN * 64 + (lane >> 4) * 8 + lr;
    const int cbB  = (lane >> 3) & 1;
    const uint32_t bRx = (uint32_t)(bRow * 128);
    const uint32_t b7  = (uint32_t)(bRow & 7);

    float acc[2][8][4];
    #pragma unroll
    for (int mt = 0; mt < 2; mt++)
        #pragma unroll
        for (int nt = 0; nt < 8; nt++)
            #pragma unroll
            for (int i = 0; i < 4; i++) acc[mt][nt][i] = 0.f;

    load_stage(0, 0);
    asm volatile("cp.async.commit_group;" ::: "memory");
    load_stage(1, 1);
    asm volatile("cp.async.commit_group;" ::: "memory");

    int sidx = 0;
    for (int kb = 0; kb < NKB; kb++) {
        if (kb < NKB - 1) {
            asm volatile("cp.async.wait_group 1;" ::: "memory");
        } else {
            asm volatile("cp.async.wait_group 0;" ::: "memory");
        }
        __syncthreads();

        const uint32_t sA = stg + sidx * STG_B;
        const uint32_t sB = sA + 16384;
        #pragma unroll
        for (int ks = 0; ks < 4; ks++) {
            uint32_t a[2][4], b[8][2];
            const uint32_t swA = ((uint32_t)(2 * ks + cbA) ^ a7) << 4;
            #pragma unroll
            for (int mt = 0; mt < 2; mt++)
                ldsm4(a[mt][0], a[mt][1], a[mt][2], a[mt][3],
                      sA + aRx + (uint32_t)(mt * 16 * 128) + swA);
            const uint32_t swB = ((uint32_t)(2 * ks + cbB) ^ b7) << 4;
            #pragma unroll
            for (int ntp = 0; ntp < 4; ntp++)
                ldsm4(b[2 * ntp][0], b[2 * ntp][1], b[2 * ntp + 1][0], b[2 * ntp + 1][1],
                      sB + bRx + (uint32_t)(ntp * 16 * 128) + swB);
            #pragma unroll
            for (int mt = 0; mt < 2; mt++)
                #pragma unroll
                for (int nt = 0; nt < 8; nt++)
                    mma_f16(acc[mt][nt], a[mt], b[nt]);
        }

        if (kb + 2 < NKB) {
            const int s2 = (sidx + 2 >= 3) ? sidx - 1 : sidx + 2;
            load_stage(s2, kb + 2);
            asm volatile("cp.async.commit_group;" ::: "memory");
        } else {
            asm volatile("cp.async.commit_group;" ::: "memory");
        }
        sidx = (sidx + 1 == 3) ? 0 : sidx + 1;
    }

    // ---- epilogue ----
    const int colblk = bx * 128 + warpN * 64;
    const int which = QKVLN ? (colblk >> 10) : 2;   // 0 q, 1 k, 2 v
    const float lnscale = (which == 0) ? qscale : 1.f;

    #pragma unroll
    for (int mt = 0; mt < 2; mt++) {
        #pragma unroll
        for (int half = 0; half < 2; half++) {
            int row = by * 128 + warpM * 32 + mt * 16 + g + half * 8;
            if (PERMROW) {
                const int t = row & 15, s = (row >> 4) & 255, bb = row >> 12;
                row = bb * 4096 + t * 256 + s;
            }
            float mean = 0.f, rstd = 1.f;
            if (QKVLN && which < 2) {
                float s1 = 0.f, s2 = 0.f;
                #pragma unroll
                for (int nt = 0; nt < 8; nt++) {
                    const float u0 = acc[mt][nt][half * 2 + 0];
                    const float u1 = acc[mt][nt][half * 2 + 1];
                    s1 += u0 + u1;
                    s2 += u0 * u0 + u1 * u1;
                }
                s1 += __shfl_xor_sync(0xffffffffu, s1, 1);
                s2 += __shfl_xor_sync(0xffffffffu, s2, 1);
                s1 += __shfl_xor_sync(0xffffffffu, s1, 2);
                s2 += __shfl_xor_sync(0xffffffffu, s2, 2);
                mean = s1 * (1.f / 64.f);
                rstd = rsqrtf(s2 * (1.f / 64.f) - mean * mean + EPSF);
            }
            const float* rpf  = (!RESH && residv) ? (const float*)residv + (size_t)row * N : nullptr;
            const __half* rph = ( RESH && residv) ? (const __half*)residv + (size_t)row * N : nullptr;
            #pragma unroll
            for (int nt = 0; nt < 8; nt++) {
                const int col = colblk + nt * 8 + tig * 2;
                float v0 = acc[mt][nt][half * 2 + 0];
                float v1 = acc[mt][nt][half * 2 + 1];
                if (QKVLN) {
                    if (which < 2) {
                        const int hc = nt * 8 + tig * 2;
                        v0 = ((v0 - mean) * rstd * hn_w[hc]     + hn_b[hc])     * lnscale;
                        v1 = ((v1 - mean) * rstd * hn_w[hc + 1] + hn_b[hc + 1]) * lnscale;
                    }
                } else {
                    if (bias) { v0 += bias[col]; v1 += bias[col + 1]; }
                    if (rpf)  { v0 += rpf[col];  v1 += rpf[col + 1]; }
                    if (rph) {
                        const float2 rr = __half22float2(*(const __half2*)(rph + col));
                        v0 += rr.x; v1 += rr.y;
                    }
                    if (GELU) {
                        v0 = 0.5f * v0 * (1.f + erff(v0 * 0.70710678f));
                        v1 = 0.5f * v1 * (1.f + erff(v1 * 0.70710678f));
                    }
                }
                if (HALFOUT) {
                    __half* cp = (__half*)Cv + (size_t)row * N + col;
                    *(uint32_t*)cp = h2pack(v0, v1);
                } else {
                    float* cp = (float*)Cv + (size_t)row * N + col;
                    float2 v; v.x = v0; v.y = v1;
                    *(float2*)cp = v;
                }
            }
        }
    }
}

// ============================================================
extern "C" void kernel_launch(void* const* d_in, const int* /*in_sizes*/, int /*n_in*/,
                              void* d_out, int /*out_size*/)
{
    const float* x        = (const float*)d_in[0];
    const float* ns_w     = (const float*)d_in[1];
    const float* ns_b     = (const float*)d_in[2];
    const float* nt_w     = (const float*)d_in[3];
    const float* nt_b     = (const float*)d_in[4];
    const float* nm_w     = (const float*)d_in[5];
    const float* nm_b     = (const float*)d_in[6];
    const float* s_qkv    = (const float*)d_in[7];
    const float* s_qkn_w  = (const float*)d_in[8];
    const float* s_qkn_b  = (const float*)d_in[9];
    const float* s_proj_w = (const float*)d_in[10];
    const float* s_proj_b = (const float*)d_in[11];
    const float* t_qkv    = (const float*)d_in[12];
    const float* t_qkn_w  = (const float*)d_in[13];
    const float* t_qkn_b  = (const float*)d_in[14];
    const float* t_proj_w = (const float*)d_in[15];
    const float* t_proj_b = (const float*)d_in[16];
    const float* fc1_w    = (const float*)d_in[17];
    const float* fc1_b    = (const float*)d_in[18];
    const float* fc2_w    = (const float*)d_in[19];
    const float* fc2_b    = (const float*)d_in[20];
    float* out = (float*)d_out;

    __half *xbuf, *xln, *qkv, *attn, *hbuf;
    __half *wt_sqkv, *wt_sproj, *wt_tqkv, *wt_tproj, *wt_fc1, *wt_fc2;
    cudaGetSymbolAddress((void**)&xbuf, g_xbuf);
    cudaGetSymbolAddress((void**)&xln,  g_xln);
    cudaGetSymbolAddress((void**)&qkv,  g_qkv);
    cudaGetSymbolAddress((void**)&attn, g_attn);
    cudaGetSymbolAddress((void**)&hbuf, g_h);
    cudaGetSymbolAddress((void**)&wt_sqkv,  g_wt_sqkv);
    cudaGetSymbolAddress((void**)&wt_sproj, g_wt_sproj);
    cudaGetSymbolAddress((void**)&wt_tqkv,  g_wt_tqkv);
    cudaGetSymbolAddress((void**)&wt_tproj, g_wt_tproj);
    cudaGetSymbolAddress((void**)&wt_fc1,   g_wt_fc1);
    cudaGetSymbolAddress((void**)&wt_fc2,   g_wt_fc2);

    cudaFuncSetAttribute(attn_tc, cudaFuncAttributeMaxDynamicSharedMemorySize, ATTN_SMEM);
    cudaFuncSetAttribute((const void*)gemm_mma<false, true,  false, true,  false>,
                         cudaFuncAttributeMaxDynamicSharedMemorySize, GEMM_SMEM);
    cudaFuncSetAttribute((const void*)gemm_mma<false, true,  false, false, false>,
                         cudaFuncAttributeMaxDynamicSharedMemorySize, GEMM_SMEM);
    cudaFuncSetAttribute((const void*)gemm_mma<false, true,  true,  false, true>,
                         cudaFuncAttributeMaxDynamicSharedMemorySize, GEMM_SMEM);
    cudaFuncSetAttribute((const void*)gemm_mma<true,  true,  false, false, false>,
                         cudaFuncAttributeMaxDynamicSharedMemorySize, GEMM_SMEM);
    cudaFuncSetAttribute((const void*)gemm_mma<false, false, false, false, true>,
                         cudaFuncAttributeMaxDynamicSharedMemorySize, GEMM_SMEM);

    // ---- all 6 weight transposes (+ fp16 rounding) in one launch ----
    TWPack pk;
    int base = 0;
    auto mk = [&](const float* in, __half* o, int K, int N) {
        TWJob j; j.in = in; j.out = o; j.K = K; j.N = N; j.ntx = N / 32; j.base = base;
        base += (N / 32) * (K / 32);
        return j;
    };
    pk.j[0] = mk(s_qkv,    wt_sqkv,  1024, 3072);
    pk.j[1] = mk(s_proj_w, wt_sproj, 1024, 1024);
    pk.j[2] = mk(t_qkv,    wt_tqkv,  1024, 3072);
    pk.j[3] = mk(t_proj_w, wt_tproj, 1024, 1024);
    pk.j[4] = mk(fc1_w,    wt_fc1,   1024, 4096);
    pk.j[5] = mk(fc2_w,    wt_fc2,   4096, 1024);
    transpose_all<<<base, dim3(32, 8)>>>(pk);

    // ---- spatial attention block ----
    ln_kernel<<<R_ / 8, 256>>>(x, xln, ns_w, ns_b);
    gemm_mma<false, true, false, true, false><<<dim3(24, 64), 256, GEMM_SMEM>>>(
        xln, wt_sqkv, qkv, nullptr, nullptr, R_, 3072, 1024, s_qkn_w, s_qkn_b, SCALE_);
    attn_tc<<<B_ * T_ * H_ * 2, 256, ATTN_SMEM>>>(qkv, attn);
    gemm_mma<false, true, false, false, false><<<dim3(8, 64), 256, GEMM_SMEM>>>(
        attn, wt_sproj, xbuf, s_proj_b, x, R_, 1024, 1024, nullptr, nullptr, 1.f);

    // ---- temporal attention block (permutes fused into ln + gemm) ----
    ln_h_kernel<true><<<R_ / 8, 256>>>(xbuf, xln, nt_w, nt_b);
    gemm_mma<false, true, false, true, false><<<dim3(24, 64), 256, GEMM_SMEM>>>(
        xln, wt_tqkv, qkv, nullptr, nullptr, R_, 3072, 1024, t_qkn_w, t_qkn_b, SCALE_);
    attn16_kernel<<<(B_ * S_ * H_) / 16, 256>>>(qkv, attn);
    gemm_mma<false, true, true, false, true><<<dim3(8, 64), 256, GEMM_SMEM>>>(
        attn, wt_tproj, xbuf, t_proj_b, xbuf, R_, 1024, 1024, nullptr, nullptr, 1.f);

    // ---- MLP ----
    ln_h_kernel<false><<<R_ / 8, 256>>>(xbuf, xln, nm_w, nm_b);
    gemm_mma<true, true, false, false, false><<<dim3(32, 64), 256, GEMM_SMEM>>>(
        xln, wt_fc1, hbuf, fc1_b, nullptr, R_, 4096, 1024, nullptr, nullptr, 1.f);
    gemm_mma<false, false, false, false, true><<<dim3(8, 64), 256, GEMM_SMEM>>>(
        hbuf, wt_fc2, out, fc2_b, xbuf, R_, 1024, 4096, nullptr, nullptr, 1.f);
}